// round 10
// baseline (speedup 1.0000x reference)
#include <cuda_runtime.h>

// Problem constants (fixed by the reference)
#define NU 8192
#define NI 8192
#define D 32
#define KC 32
#define BIASF 0.1f

#define NB 256     // blocks: 32 user-rows + 256 output-float4s each
#define NT 256     // 8 warps

// Scratch (__device__ globals). Partials are fully overwritten every launch;
// only g_ctr needs reset (done by the last block) -> graph-replay safe.
__device__ float g_pmax[NB * KC];   // per-block partial col max(exp(logit))
__device__ float g_psum[NB * KC];   // per-block partial col sum(exp(logit))
__device__ unsigned g_ctr;          // last-block counter

__global__ void __launch_bounds__(NT) k_fused(const float* __restrict__ U,
                                              const float* __restrict__ Iemb,
                                              const float* __restrict__ Kw,
                                              const float* __restrict__ Kb,
                                              const float* __restrict__ Qw,
                                              const float* __restrict__ Qb,
                                              const float* __restrict__ Rw,
                                              const float* __restrict__ Rb,
                                              float* __restrict__ out)
{
    __shared__ float sKw[D * KC];       // Kw staged once per block
    __shared__ float sM[8][33], sS[8][33];
    __shared__ float sZ[KC], sME[KC];   // folded stats (last block only)
    __shared__ int sLast;

    const int t = threadIdx.x, lane = t & 31, w = t >> 5;

    // ---- issue ALL long-latency loads up front (max MLP) ----
    const size_t j = (size_t)blockIdx.x * NT + t;          // output float4 index
    const float4 i4  = ((const float4*)Iemb)[j];
    const float4 rb4 = ((const float4*)Rb)[j & 7];

    const int row0 = blockIdx.x * 32 + w * 4;              // this warp's 4 user rows
    float uval[4];
#pragma unroll
    for (int i = 0; i < 4; i++)
        uval[i] = U[(size_t)(row0 + i) * D + lane];

    // Stage Kw cooperatively (4 floats/thread) — one LDG stream per block.
#pragma unroll
    for (int i = 0; i < 4; i++) sKw[t + i * NT] = Kw[t + i * NT];
    const float kb = Kb[lane];
    __syncthreads();

    // ---- optimistic fast-path output (independent of the stats) ----
    // If the global bound (verified by the last block) holds, the exact result
    // for EVERY item is out = I + reproj_b:
    //   dot(u,i,h) = sum_c k[u,c] q[i,c] <= max_c (maxe_c/Z_c) <= BIAS
    //   (q >= 0, sum_c q = 1 per head)  =>  relu(dot - BIAS) == 0 everywhere.
    ((float4*)out)[j] = make_float4(i4.x + rb4.x, i4.y + rb4.y,
                                    i4.z + rb4.z, i4.w + rb4.w);

    // ---- keys shuffle-dot: logit(row0+i, col=lane) ----
    float acc[4];
#pragma unroll
    for (int i = 0; i < 4; i++) acc[i] = kb;
#pragma unroll
    for (int d = 0; d < D; d++) {
        const float kwd = sKw[d * KC + lane];   // LDS, conflict-free
#pragma unroll
        for (int i = 0; i < 4; i++)
            acc[i] = fmaf(__shfl_sync(0xffffffffu, uval[i], d), kwd, acc[i]);
    }
    // Logits tiny (|l| < ~4) -> unshifted exp safe; exp monotone.
    float m = 0.0f, s = 0.0f;
#pragma unroll
    for (int i = 0; i < 4; i++) {
        float ev = __expf(acc[i]);
        m = fmaxf(m, ev); s += ev;
    }
    sM[w][lane] = m; sS[w][lane] = s;
    __syncthreads();

    // Block partials -> plain stores (NO contended atomics).
    if (t < KC) {
        float mm = sM[0][t], ss = sS[0][t];
#pragma unroll
        for (int g = 1; g < 8; g++) { mm = fmaxf(mm, sM[g][t]); ss += sS[g][t]; }
        g_pmax[blockIdx.x * KC + t] = mm;
        g_psum[blockIdx.x * KC + t] = ss;
    }
    __threadfence();                    // publish partials + output slice
    __syncthreads();
    if (t == 0) sLast = (atomicAdd(&g_ctr, 1u) == (unsigned)(NB - 1));
    __syncthreads();
    if (!sLast) return;                 // no spinning; deadlock-impossible

    // ================= LAST BLOCK: fold + verify ===========================
    {   // thread (c = t&31, g = t>>5) folds 32 blocks; 8 groups cover all 256.
        const int c = t & 31, g = t >> 5;
        float mm = 0.0f, ss = 0.0f;
        for (int b = g * 32; b < g * 32 + 32; b++) {
            mm = fmaxf(mm, __ldcg(&g_pmax[b * KC + c]));
            ss += __ldcg(&g_psum[b * KC + c]);
        }
        sM[g][c] = mm; sS[g][c] = ss;
    }
    __syncthreads();
    int hv = 0;
    if (t < KC) {
        float mm = sM[0][t], ss = sS[0][t];
#pragma unroll
        for (int g = 1; g < 8; g++) { mm = fmaxf(mm, sM[g][t]); ss += sS[g][t]; }
        sME[t] = mm; sZ[t] = ss;
        hv = (mm > BIASF * ss);         // heavy <=> max_c maxe_c/Z_c > BIAS
    }
    const int heavy = __syncthreads_or(hv);

    if (heavy) {
        // SLOW PATH (honest full computation, overwrites out; block-uniform;
        // never taken for these inputs — bound margin ~100x).
        const float zs = sZ[lane];
        const float iz = 1.0f / zs;
        const float cm = sME[lane] * iz;
        float qwv[D];
#pragma unroll
        for (int d = 0; d < D; d++) qwv[d] = Qw[d * KC + lane];
        const float qb = Qb[lane], rbs = Rb[lane];

        for (int item = w; item < NI; item += 8) {           // warp-per-item
            const float e = Iemb[(size_t)item * D + lane];
            float a2 = qb;
#pragma unroll
            for (int d = 0; d < D; d++)
                a2 = fmaf(__shfl_sync(0xffffffffu, e, d), qwv[d], a2);
            float mx = a2;
            mx = fmaxf(mx, __shfl_xor_sync(0xffffffffu, mx, 1));
            mx = fmaxf(mx, __shfl_xor_sync(0xffffffffu, mx, 2));
            mx = fmaxf(mx, __shfl_xor_sync(0xffffffffu, mx, 4));
            float q = __expf(a2 - mx);
            float ssum = q;
            ssum += __shfl_xor_sync(0xffffffffu, ssum, 1);
            ssum += __shfl_xor_sync(0xffffffffu, ssum, 2);
            ssum += __shfl_xor_sync(0xffffffffu, ssum, 4);
            q /= ssum;

            // per-item refined bound: skip user loop when provably zero
            float ubp = q * cm;
            ubp += __shfl_xor_sync(0xffffffffu, ubp, 1);
            ubp += __shfl_xor_sync(0xffffffffu, ubp, 2);
            ubp += __shfl_xor_sync(0xffffffffu, ubp, 4);
            if (!__any_sync(0xffffffffu, ubp > BIASF)) {
                out[(size_t)item * KC + lane] = e + rbs;
                continue;
            }

            const float kbs = Kb[lane];
            float att0 = 0.f, att1 = 0.f, att2 = 0.f, att3 = 0.f;  // att[h], d=lane
            for (int u = 0; u < NU; u++) {
                float uv = U[(size_t)u * D + lane];
                float kl = kbs;
#pragma unroll
                for (int d = 0; d < D; d++)
                    kl = fmaf(__shfl_sync(0xffffffffu, uv, d), sKw[d * KC + lane], kl);
                float kk = __expf(kl) * iz;
                float p = kk * q;
                p += __shfl_xor_sync(0xffffffffu, p, 1);
                p += __shfl_xor_sync(0xffffffffu, p, 2);
                p += __shfl_xor_sync(0xffffffffu, p, 4);
                float wgt = fmaxf(p - BIASF, 0.0f);
                float w0 = __shfl_sync(0xffffffffu, wgt, 0);
                float w1 = __shfl_sync(0xffffffffu, wgt, 8);
                float w2 = __shfl_sync(0xffffffffu, wgt, 16);
                float w3 = __shfl_sync(0xffffffffu, wgt, 24);
                att0 = fmaf(w0, uv, att0);
                att1 = fmaf(w1, uv, att1);
                att2 = fmaf(w2, uv, att2);
                att3 = fmaf(w3, uv, att3);
            }
            float o = rbs;
#pragma unroll
            for (int hh = 0; hh < 4; hh++) {
                float ah = (hh == 0) ? att0 : (hh == 1) ? att1 : (hh == 2) ? att2 : att3;
                for (int d2 = 0; d2 < D; d2++) {
                    float a = __shfl_sync(0xffffffffu, ah, d2);
                    o = fmaf(a, Rw[(hh * D + d2) * KC + lane], o);
                }
            }
            out[(size_t)item * KC + lane] = e + o;
        }
        __syncthreads();
    }

    // ---- reset for next launch / graph replay ----
    if (t == 0) g_ctr = 0u;
}

// ---------------------------------------------------------------------------
extern "C" void kernel_launch(void* const* d_in, const int* in_sizes, int n_in,
                              void* d_out, int out_size)
{
    (void)in_sizes; (void)n_in; (void)out_size;
    const float* U  = (const float*)d_in[0];
    const float* I  = (const float*)d_in[1];
    const float* Kw = (const float*)d_in[2];
    const float* Kb = (const float*)d_in[3];
    const float* Qw = (const float*)d_in[4];
    const float* Qb = (const float*)d_in[5];
    const float* Rw = (const float*)d_in[6];
    const float* Rb = (const float*)d_in[7];
    float* out = (float*)d_out;

    k_fused<<<NB, NT>>>(U, I, Kw, Kb, Qw, Qb, Rw, Rb, out);
}